// round 1
// baseline (speedup 1.0000x reference)
#include <cuda_runtime.h>
#include <math_constants.h>

#define NPTS   32768
#define KCODES 1024
#define DIM    256
#define HW     1024

// output offsets (flattened tuple, float32)
#define OFF_ZQ    0ul
#define OFF_LOSS  8388608ul
#define OFF_IDX   8388609ul
#define OFF_EMB   8421377ul
#define OFF_CS    8683521ul
#define OFF_ES    8684545ul

// scratch (device globals: no allocation allowed)
__device__ float g_zz[NPTS];
__device__ float g_ee[KCODES];
__device__ int   g_idx[NPTS];
__device__ float g_es[KCODES * DIM];
__device__ float g_counts[KCODES];
__device__ float g_loss;
__device__ float g_nsum;
__device__ float g_newcs[KCODES];

// ---------------- zero scratch accumulators (graph replays!) ----------------
__global__ void k_zero() {
    int i = blockIdx.x * 256 + threadIdx.x;
    if (i < KCODES * DIM) g_es[i] = 0.f;
    else if (i < KCODES * DIM + KCODES) g_counts[i - KCODES * DIM] = 0.f;
    else if (i == KCODES * DIM + KCODES) g_loss = 0.f;
    else if (i == KCODES * DIM + KCODES + 1) g_nsum = 0.f;
}

// ---------------- ||e_k||^2 ----------------
__global__ void k_ee(const float* __restrict__ E) {
    int w = (blockIdx.x * blockDim.x + threadIdx.x) >> 5;
    int lane = threadIdx.x & 31;
    if (w >= KCODES) return;
    const float* row = E + (size_t)w * DIM;
    float s = 0.f;
#pragma unroll
    for (int i = 0; i < 8; i++) { float v = row[lane + i * 32]; s = fmaf(v, v, s); }
#pragma unroll
    for (int o = 16; o; o >>= 1) s += __shfl_xor_sync(0xffffffffu, s, o);
    if (!lane) g_ee[w] = s;
}

// ---------------- ||z_n||^2 (coalesced: lanes along hw) ----------------
__global__ void k_zz(const float* __restrict__ z) {
    int n = blockIdx.x * 256 + threadIdx.x;
    int b = n >> 10, hw = n & 1023;
    const float* p = z + (size_t)b * DIM * HW + hw;
    float s = 0.f;
#pragma unroll 8
    for (int d = 0; d < DIM; d++) { float v = p[(size_t)d * HW]; s = fmaf(v, v, s); }
    g_zz[n] = s;
}

// ---------------- distance GEMM + argmin ----------------
// block: 128 points x (all 1024 codes in 8 tiles of 128). 256 threads, 8x8 microtile.
__global__ __launch_bounds__(256, 2)
void k_gemm(const float* __restrict__ z, const float* __restrict__ E,
            float* __restrict__ out) {
    __shared__ float As[8][128];
    __shared__ float Bs[8][128];
    __shared__ float sVal[16][128];
    __shared__ int   sIdx[16][128];

    const int tid = threadIdx.x;
    const int n0 = blockIdx.x * 128;
    const int b = n0 >> 10, hw0 = n0 & 1023;
    const float* zbase = z + (size_t)b * DIM * HW + hw0;

    const int tx = tid & 15;   // code group (8 codes)
    const int ty = tid >> 4;   // point group (8 points)

    float best[8]; int bidx[8];
#pragma unroll
    for (int i = 0; i < 8; i++) { best[i] = CUDART_INF_F; bidx[i] = 0; }

    float zzv[8];
#pragma unroll
    for (int i = 0; i < 8; i++) zzv[i] = g_zz[n0 + ty * 8 + i];

    for (int kt = 0; kt < 8; ++kt) {
        float acc[8][8];
#pragma unroll
        for (int i = 0; i < 8; i++)
#pragma unroll
            for (int j = 0; j < 8; j++) acc[i][j] = 0.f;

        for (int d0 = 0; d0 < DIM; d0 += 8) {
            // As[dk][pt] <- z[b, d0+dk, hw0+pt]  (coalesced along pt)
#pragma unroll
            for (int r = 0; r < 4; ++r) {
                int dk = (tid >> 7) + r * 2;
                int pt = tid & 127;
                As[dk][pt] = zbase[(size_t)(d0 + dk) * HW + pt];
            }
            // Bs[dk][k] <- E[kt*128+k][d0+dk]  (float4 along d)
            {
                int k = tid >> 1;
                int dk4 = (tid & 1) * 4;
                float4 v = *reinterpret_cast<const float4*>(
                    &E[(size_t)(kt * 128 + k) * DIM + d0 + dk4]);
                Bs[dk4 + 0][k] = v.x; Bs[dk4 + 1][k] = v.y;
                Bs[dk4 + 2][k] = v.z; Bs[dk4 + 3][k] = v.w;
            }
            __syncthreads();
#pragma unroll
            for (int kk = 0; kk < 8; ++kk) {
                float4 a0 = *reinterpret_cast<const float4*>(&As[kk][ty * 8]);
                float4 a1 = *reinterpret_cast<const float4*>(&As[kk][ty * 8 + 4]);
                float4 b0 = *reinterpret_cast<const float4*>(&Bs[kk][tx * 8]);
                float4 b1 = *reinterpret_cast<const float4*>(&Bs[kk][tx * 8 + 4]);
                float a[8] = {a0.x, a0.y, a0.z, a0.w, a1.x, a1.y, a1.z, a1.w};
                float bb[8] = {b0.x, b0.y, b0.z, b0.w, b1.x, b1.y, b1.z, b1.w};
#pragma unroll
                for (int i = 0; i < 8; i++)
#pragma unroll
                    for (int j = 0; j < 8; j++)
                        acc[i][j] = fmaf(a[i], bb[j], acc[i][j]);
            }
            __syncthreads();
        }
        // fold this code tile into running argmin (mimic ref: (zz - 2*dot) + ee)
#pragma unroll
        for (int j = 0; j < 8; j++) {
            int code = kt * 128 + tx * 8 + j;
            float eev = g_ee[code];
#pragma unroll
            for (int i = 0; i < 8; i++) {
                float m = __fmul_rn(2.0f, acc[i][j]);
                float t = __fadd_rn(zzv[i], -m);
                float dist = __fadd_rn(t, eev);
                if (dist < best[i]) { best[i] = dist; bidx[i] = code; }
            }
        }
    }
    // cross-thread argmin per point, tie-break = lowest index (matches jnp.argmin)
#pragma unroll
    for (int i = 0; i < 8; i++) {
        sVal[tx][ty * 8 + i] = best[i];
        sIdx[tx][ty * 8 + i] = bidx[i];
    }
    __syncthreads();
    if (tid < 128) {
        float bv = sVal[0][tid]; int bi = sIdx[0][tid];
#pragma unroll
        for (int t = 1; t < 16; t++) {
            float v = sVal[t][tid]; int ix = sIdx[t][tid];
            if (v < bv || (v == bv && ix < bi)) { bv = v; bi = ix; }
        }
        g_idx[n0 + tid] = bi;
        out[OFF_IDX + n0 + tid] = (float)bi;
    }
}

// ---------------- fused epilogue: gather z_q, loss, counts, embed_sum ----------------
// block: 128 points, 4 d-chunks of 64. warp-per-point phase for coalesced E/atomics.
__global__ __launch_bounds__(256)
void k_epi(const float* __restrict__ z, const float* __restrict__ E,
           float* __restrict__ out) {
    __shared__ float tile[64 * 129];
    __shared__ float lred[8];
    const int tid = threadIdx.x;
    const int n0 = blockIdx.x * 128;
    const int b = n0 >> 10, hw0 = n0 & 1023;
    const float* zb = z + (size_t)b * DIM * HW + hw0;
    float* ob = out + OFF_ZQ + (size_t)b * DIM * HW + hw0;
    const int w = tid >> 5, lane = tid & 31;
    float lacc = 0.f;

    for (int c = 0; c < 4; c++) {
        // cooperative load z chunk (64 d x 128 pts), coalesced along pt
#pragma unroll
        for (int r = 0; r < 32; r++) {
            int idx = tid + r * 256;
            int dd = idx >> 7, pt = idx & 127;
            tile[dd * 129 + pt] = zb[(size_t)(c * 64 + dd) * HW + pt];
        }
        __syncthreads();
        // warp w handles pts w*16..w*16+15; lanes along d (coalesced E + REDG)
        for (int q = 0; q < 16; q++) {
            int pt = w * 16 + q;
            int code = g_idx[n0 + pt];
            int d = c * 64 + lane * 2;
            float2 ev = *reinterpret_cast<const float2*>(&E[(size_t)code * DIM + d]);
            float z0 = tile[(lane * 2) * 129 + pt];
            float z1 = tile[(lane * 2 + 1) * 129 + pt];
            float d0 = __fadd_rn(z0, -ev.x);
            float d1 = __fadd_rn(z1, -ev.y);
            lacc = fmaf(d0, d0, lacc);
            lacc = fmaf(d1, d1, lacc);
            // straight-through: z + (z_q - z), op-for-op like reference
            float o0 = __fadd_rn(z0, __fadd_rn(ev.x, -z0));
            float o1 = __fadd_rn(z1, __fadd_rn(ev.y, -z1));
            tile[(lane * 2) * 129 + pt] = o0;
            tile[(lane * 2 + 1) * 129 + pt] = o1;
            atomicAdd(reinterpret_cast<float2*>(&g_es[(size_t)code * DIM + d]),
                      make_float2(z0, z1));
        }
        __syncthreads();
        // cooperative store z_q_st chunk
#pragma unroll
        for (int r = 0; r < 32; r++) {
            int idx = tid + r * 256;
            int dd = idx >> 7, pt = idx & 127;
            ob[(size_t)(c * 64 + dd) * HW + pt] = tile[dd * 129 + pt];
        }
        __syncthreads();
    }
    if (tid < 128) atomicAdd(&g_counts[g_idx[n0 + tid]], 1.0f);
#pragma unroll
    for (int o = 16; o; o >>= 1) lacc += __shfl_xor_sync(0xffffffffu, lacc, o);
    if (!lane) lred[w] = lacc;
    __syncthreads();
    if (tid == 0) {
        float s = 0.f;
#pragma unroll
        for (int i = 0; i < 8; i++) s += lred[i];
        atomicAdd(&g_loss, s);
    }
}

// ---------------- new_cs + n + loss scalar ----------------
__global__ void k4a(const float* __restrict__ ema_cs, float* __restrict__ out) {
    __shared__ float red[32];
    int k = threadIdx.x;
    float ncs = __fadd_rn(__fmul_rn(0.99f, ema_cs[k]), __fmul_rn(0.01f, g_counts[k]));
    g_newcs[k] = ncs;
    out[OFF_CS + k] = ncs;
    float s = ncs;
#pragma unroll
    for (int o = 16; o; o >>= 1) s += __shfl_xor_sync(0xffffffffu, s, o);
    if ((k & 31) == 0) red[k >> 5] = s;
    __syncthreads();
    if (k < 32) {
        float v = red[k];
#pragma unroll
        for (int o = 16; o; o >>= 1) v += __shfl_xor_sync(0xffffffffu, v, o);
        if (!k) {
            g_nsum = v;
            out[OFF_LOSS] = g_loss * (1.0f / 8388608.0f);
        }
    }
}

// ---------------- new_es + new_embedding ----------------
__global__ void k4b(const float* __restrict__ ema_es, float* __restrict__ out) {
    int k = blockIdx.x, d = threadIdx.x;
    size_t i = (size_t)k * DIM + d;
    float es = __fadd_rn(__fmul_rn(0.99f, ema_es[i]), __fmul_rn(0.01f, g_es[i]));
    out[OFF_ES + i] = es;
    float n = g_nsum;
    float cs = __fmul_rn(__fdiv_rn(__fadd_rn(g_newcs[k], 1e-5f),
                                   __fadd_rn(n, 0.01024f)), n);
    out[OFF_EMB + i] = __fdiv_rn(es, cs);
}

extern "C" void kernel_launch(void* const* d_in, const int* in_sizes, int n_in,
                              void* d_out, int out_size) {
    const float* z      = (const float*)d_in[0];
    const float* E      = (const float*)d_in[1];
    const float* ema_cs = (const float*)d_in[2];
    const float* ema_es = (const float*)d_in[3];
    float* out = (float*)d_out;

    k_zero<<<(KCODES * DIM + KCODES + 2 + 255) / 256, 256>>>();
    k_ee<<<128, 256>>>(E);
    k_zz<<<128, 256>>>(z);
    k_gemm<<<NPTS / 128, 256>>>(z, E, out);
    k_epi<<<NPTS / 128, 256>>>(z, E, out);
    k4a<<<1, 1024>>>(ema_cs, out);
    k4b<<<KCODES, DIM>>>(ema_es, out);
}

// round 5
// speedup vs baseline: 1.0647x; 1.0647x over previous
#include <cuda_runtime.h>
#include <math_constants.h>
#include <cstdint>

#define NPTS   32768
#define KCODES 1024
#define DIM    256
#define HW     1024

#define OFF_ZQ    0ul
#define OFF_LOSS  8388608ul
#define OFF_IDX   8388609ul
#define OFF_EMB   8421377ul
#define OFF_CS    8683521ul
#define OFF_ES    8684545ul

#define EPS_GAP 2e-4f

// ---------------- device scratch ----------------
__device__ float g_zz[NPTS];
__device__ float g_ee[KCODES];
__device__ int   g_idx[NPTS];
__device__ int   g_idx2[NPTS];
__device__ int   g_fixlist[NPTS];
__device__ int   g_fixn;
__device__ float g_es[KCODES * DIM];
__device__ float g_counts[KCODES];
__device__ float g_loss;
__device__ float g_nsum;
__device__ float g_newcs[KCODES];

// tf32 splits: z as [d][n] (n contiguous), E transposed as [d][code]
__device__ uint32_t g_zhi[DIM * NPTS];
__device__ uint32_t g_zlo[DIM * NPTS];
__device__ uint32_t g_ehiT[DIM * KCODES];
__device__ uint32_t g_eloT[DIM * KCODES];

// ---------------- helpers ----------------
__device__ __forceinline__ uint32_t f2tf32(float x) {
    uint32_t r; asm("cvt.rna.tf32.f32 %0, %1;" : "=r"(r) : "f"(x)); return r;
}
__device__ __forceinline__ uint32_t smem_u32(const void* p) {
    uint32_t a;
    asm("{ .reg .u64 t; cvta.to.shared.u64 t, %1; cvt.u32.u64 %0, t; }" : "=r"(a) : "l"(p));
    return a;
}
__device__ __forceinline__ void cp16(uint32_t dst, const void* src) {
    asm volatile("cp.async.cg.shared.global [%0], [%1], 16;" :: "r"(dst), "l"(src));
}
#define CP_COMMIT() asm volatile("cp.async.commit_group;" ::: "memory")
#define CP_WAIT1()  asm volatile("cp.async.wait_group 1;" ::: "memory")
#define CP_WAIT0()  asm volatile("cp.async.wait_group 0;" ::: "memory")

__device__ __forceinline__ void mma8(float* c, const uint32_t* a, const uint32_t* b) {
    asm volatile(
        "mma.sync.aligned.m16n8k8.row.col.f32.tf32.tf32.f32 "
        "{%0,%1,%2,%3}, {%4,%5,%6,%7}, {%8,%9}, {%0,%1,%2,%3};"
        : "+f"(c[0]), "+f"(c[1]), "+f"(c[2]), "+f"(c[3])
        : "r"(a[0]), "r"(a[1]), "r"(a[2]), "r"(a[3]), "r"(b[0]), "r"(b[1]));
}

// top-2 insert with jnp.argmin tie-break (lowest index wins on equal value)
__device__ __forceinline__ void ins2(float& b0v, int& b0i, float& b1v, int& b1i,
                                     float v, int ix) {
    if (v < b0v || (v == b0v && ix < b0i)) {
        b1v = b0v; b1i = b0i; b0v = v; b0i = ix;
    } else if (v < b1v || (v == b1v && ix < b1i)) {
        b1v = v; b1i = ix;
    }
}

// ---------------- zero accumulators (graph replays!) ----------------
__global__ void k_zero() {
    int i = blockIdx.x * 256 + threadIdx.x;
    if (i < KCODES * DIM) g_es[i] = 0.f;
    else if (i < KCODES * DIM + KCODES) g_counts[i - KCODES * DIM] = 0.f;
    else if (i == KCODES * DIM + KCODES) g_loss = 0.f;
    else if (i == KCODES * DIM + KCODES + 1) g_nsum = 0.f;
    else if (i == KCODES * DIM + KCODES + 2) g_fixn = 0;
}

// ---------------- ||e_k||^2 ----------------
__global__ void k_ee(const float* __restrict__ E) {
    int w = (blockIdx.x * blockDim.x + threadIdx.x) >> 5;
    int lane = threadIdx.x & 31;
    if (w >= KCODES) return;
    const float* row = E + (size_t)w * DIM;
    float s = 0.f;
#pragma unroll
    for (int i = 0; i < 8; i++) { float v = row[lane + i * 32]; s = fmaf(v, v, s); }
#pragma unroll
    for (int o = 16; o; o >>= 1) s += __shfl_xor_sync(0xffffffffu, s, o);
    if (!lane) g_ee[w] = s;
}

// ---------------- ||z_n||^2 ----------------
__global__ void k_zz(const float* __restrict__ z) {
    int n = blockIdx.x * 256 + threadIdx.x;
    int b = n >> 10, hw = n & 1023;
    const float* p = z + (size_t)b * DIM * HW + hw;
    float s = 0.f;
#pragma unroll 8
    for (int d = 0; d < DIM; d++) { float v = p[(size_t)d * HW]; s = fmaf(v, v, s); }
    g_zz[n] = s;
}

// ---------------- split z -> tf32 hi/lo in [d][n] ----------------
__global__ void k_split_z(const float4* __restrict__ z4) {
    int i = blockIdx.x * 256 + threadIdx.x;    // over 2097152 float4s
    float4 v = z4[i];
    int e0 = i * 4;
    int b = e0 >> 18;          // / (DIM*HW)
    int r = e0 & 262143;
    int d = r >> 10;
    int hw = r & 1023;
    uint32_t dst = (uint32_t)d * NPTS + (uint32_t)b * 1024u + (uint32_t)hw;
    uint4 h, l;
    h.x = f2tf32(v.x); l.x = f2tf32(v.x - __uint_as_float(h.x));
    h.y = f2tf32(v.y); l.y = f2tf32(v.y - __uint_as_float(h.y));
    h.z = f2tf32(v.z); l.z = f2tf32(v.z - __uint_as_float(h.z));
    h.w = f2tf32(v.w); l.w = f2tf32(v.w - __uint_as_float(h.w));
    *reinterpret_cast<uint4*>(&g_zhi[dst]) = h;
    *reinterpret_cast<uint4*>(&g_zlo[dst]) = l;
}

// ---------------- split E -> tf32 hi/lo transposed [d][code] ----------------
__global__ void k_split_eT(const float* __restrict__ E) {
    int i = blockIdx.x * 256 + threadIdx.x;    // over 262144
    float v = E[i];
    int code = i >> 8, d = i & 255;
    uint32_t h = f2tf32(v);
    uint32_t l = f2tf32(v - __uint_as_float(h));
    g_ehiT[d * KCODES + code] = h;
    g_eloT[d * KCODES + code] = l;
}

// ---------------- tf32x3 mma.sync distance GEMM + top-2 argmin ----------------
// 128 CTAs x 256 pts x 1024 codes. 8 warps as 4(m)x2(n), warp tile 64x64.
// K chunks of 32 dims, cp.async double buffer.
#define AM 260
#define BN 132
#define SM_ZZ    0
#define SM_EE    1024
#define SM_RED   5120
#define SM_STAGE 13312
#define ABYTES   (32 * AM * 4)                    // 33280
#define BBYTES   (32 * BN * 4)                    // 16896
#define STAGE_BYTES (2 * ABYTES + 2 * BBYTES)     // 100352
#define SMEM_GEMM   (SM_STAGE + 2 * STAGE_BYTES)  // 214016

__device__ __forceinline__ void load_stage(uint32_t sbase, int cid, int kt, int kc, int tid) {
    int d0 = kc * 32;
    const uint32_t* zh = g_zhi + (size_t)d0 * NPTS + cid * 256;
    const uint32_t* zl = g_zlo + (size_t)d0 * NPTS + cid * 256;
#pragma unroll
    for (int j = 0; j < 8; j++) {
        int i = tid + j * 256;
        int r = i >> 6, c = i & 63;
        cp16(sbase + r * 1040 + c * 16, zh + (size_t)r * NPTS + c * 4);
        cp16(sbase + ABYTES + r * 1040 + c * 16, zl + (size_t)r * NPTS + c * 4);
    }
    const uint32_t* eh = g_ehiT + (size_t)d0 * KCODES + kt * 128;
    const uint32_t* el = g_eloT + (size_t)d0 * KCODES + kt * 128;
#pragma unroll
    for (int j = 0; j < 4; j++) {
        int i = tid + j * 256;
        int r = i >> 5, c = i & 31;
        cp16(sbase + 2 * ABYTES + r * 528 + c * 16, eh + (size_t)r * KCODES + c * 4);
        cp16(sbase + 2 * ABYTES + BBYTES + r * 528 + c * 16, el + (size_t)r * KCODES + c * 4);
    }
}

__global__ __launch_bounds__(256, 1) void k_gemm(float* __restrict__ out) {
    extern __shared__ uint8_t smem[];
    uint32_t sb = smem_u32(smem);
    float* s_zz = reinterpret_cast<float*>(smem + SM_ZZ);
    float* s_ee = reinterpret_cast<float*>(smem + SM_EE);
    float* sB0v = reinterpret_cast<float*>(smem + SM_RED);
    int*   sB0i = reinterpret_cast<int*>(smem + SM_RED + 2048);
    float* sB1v = reinterpret_cast<float*>(smem + SM_RED + 4096);
    int*   sB1i = reinterpret_cast<int*>(smem + SM_RED + 6144);

    const int tid = threadIdx.x, cid = blockIdx.x;
    const int lane = tid & 31, w = tid >> 5;
    const int gq = lane >> 2, tig = lane & 3;
    const int mw = (w >> 1) * 64, nw = (w & 1) * 64;

    s_zz[tid] = g_zz[cid * 256 + tid];
#pragma unroll
    for (int i = 0; i < 4; i++) s_ee[tid + 256 * i] = g_ee[tid + 256 * i];

    float acc[4][8][4];
#pragma unroll
    for (int mt = 0; mt < 4; mt++)
#pragma unroll
        for (int nt = 0; nt < 8; nt++)
#pragma unroll
            for (int q = 0; q < 4; q++) acc[mt][nt][q] = 0.f;
    float b0v[8], b1v[8]; int b0i[8], b1i[8];
#pragma unroll
    for (int i = 0; i < 8; i++) {
        b0v[i] = CUDART_INF_F; b0i[i] = 0x7fffffff;
        b1v[i] = CUDART_INF_F; b1i[i] = 0x7fffffff;
    }
    float zzv[8];

    __syncthreads();
#pragma unroll
    for (int mt = 0; mt < 4; mt++) {
        zzv[mt * 2]     = s_zz[mw + mt * 16 + gq];
        zzv[mt * 2 + 1] = s_zz[mw + mt * 16 + gq + 8];
    }

    load_stage(sb + SM_STAGE, cid, 0, 0, tid);
    CP_COMMIT();

    for (int it = 0; it < 64; it++) {
        int s = it & 1;
        if (it + 1 < 64) {
            load_stage(sb + SM_STAGE + ((it + 1) & 1) * STAGE_BYTES,
                       cid, (it + 1) >> 3, (it + 1) & 7, tid);
            CP_COMMIT();
            CP_WAIT1();
        } else {
            CP_WAIT0();
        }
        __syncthreads();

        const uint32_t* Ah = reinterpret_cast<const uint32_t*>(smem + SM_STAGE + s * STAGE_BYTES);
        const uint32_t* Al = Ah + 32 * AM;
        const uint32_t* Bh = Ah + 64 * AM;
        const uint32_t* Bl = Bh + 32 * BN;

#pragma unroll
        for (int ks = 0; ks < 4; ks++) {
            const int k0 = ks * 8 + tig;
            uint32_t a1[4][4], a2[4][4], bb[8][2];
            const uint32_t* Ak = Ah + k0 * AM + mw + gq;
#pragma unroll
            for (int mt = 0; mt < 4; mt++) {
                a1[mt][0] = Ak[mt * 16];
                a1[mt][1] = Ak[mt * 16 + 8];
                a1[mt][2] = Ak[4 * AM + mt * 16];
                a1[mt][3] = Ak[4 * AM + mt * 16 + 8];
            }
            const uint32_t* Bk = Bh + k0 * BN + nw + gq;
#pragma unroll
            for (int nt = 0; nt < 8; nt++) {
                bb[nt][0] = Bk[nt * 8];
                bb[nt][1] = Bk[4 * BN + nt * 8];
            }
            // pass 1: zh * eh
#pragma unroll
            for (int mt = 0; mt < 4; mt++)
#pragma unroll
                for (int nt = 0; nt < 8; nt++) mma8(acc[mt][nt], a1[mt], bb[nt]);
            // pass 2: zl * eh
            const uint32_t* Ak2 = Al + k0 * AM + mw + gq;
#pragma unroll
            for (int mt = 0; mt < 4; mt++) {
                a2[mt][0] = Ak2[mt * 16];
                a2[mt][1] = Ak2[mt * 16 + 8];
                a2[mt][2] = Ak2[4 * AM + mt * 16];
                a2[mt][3] = Ak2[4 * AM + mt * 16 + 8];
            }
#pragma unroll
            for (int mt = 0; mt < 4; mt++)
#pragma unroll
                for (int nt = 0; nt < 8; nt++) mma8(acc[mt][nt], a2[mt], bb[nt]);
            // pass 3: zh * el
            const uint32_t* Bk2 = Bl + k0 * BN + nw + gq;
#pragma unroll
            for (int nt = 0; nt < 8; nt++) {
                bb[nt][0] = Bk2[nt * 8];
                bb[nt][1] = Bk2[4 * BN + nt * 8];
            }
#pragma unroll
            for (int mt = 0; mt < 4; mt++)
#pragma unroll
                for (int nt = 0; nt < 8; nt++) mma8(acc[mt][nt], a1[mt], bb[nt]);
        }

        if ((it & 7) == 7) {
            int kt = it >> 3;
#pragma unroll
            for (int nt = 0; nt < 8; nt++) {
                int code0 = kt * 128 + nw + nt * 8 + 2 * tig;
                float2 ee2 = *reinterpret_cast<const float2*>(&s_ee[code0]);
#pragma unroll
                for (int mt = 0; mt < 4; mt++) {
                    float d0 = __fadd_rn(__fadd_rn(zzv[mt * 2], -__fmul_rn(2.0f, acc[mt][nt][0])), ee2.x);
                    float d1 = __fadd_rn(__fadd_rn(zzv[mt * 2], -__fmul_rn(2.0f, acc[mt][nt][1])), ee2.y);
                    float d2 = __fadd_rn(__fadd_rn(zzv[mt * 2 + 1], -__fmul_rn(2.0f, acc[mt][nt][2])), ee2.x);
                    float d3 = __fadd_rn(__fadd_rn(zzv[mt * 2 + 1], -__fmul_rn(2.0f, acc[mt][nt][3])), ee2.y);
                    int r0 = mt * 2, r1 = mt * 2 + 1;
                    ins2(b0v[r0], b0i[r0], b1v[r0], b1i[r0], d0, code0);
                    ins2(b0v[r0], b0i[r0], b1v[r0], b1i[r0], d1, code0 + 1);
                    ins2(b0v[r1], b0i[r1], b1v[r1], b1i[r1], d2, code0);
                    ins2(b0v[r1], b0i[r1], b1v[r1], b1i[r1], d3, code0 + 1);
                    acc[mt][nt][0] = 0.f; acc[mt][nt][1] = 0.f;
                    acc[mt][nt][2] = 0.f; acc[mt][nt][3] = 0.f;
                }
            }
        }
        __syncthreads();
    }

    // quad butterfly top-2 merge, then across the 2 n-warp halves
#pragma unroll
    for (int i = 0; i < 8; i++) {
        float v0 = b0v[i], v1 = b1v[i]; int i0 = b0i[i], i1 = b1i[i];
#pragma unroll
        for (int o = 1; o <= 2; o <<= 1) {
            float ov0 = __shfl_xor_sync(0xffffffffu, v0, o);
            int   oi0 = __shfl_xor_sync(0xffffffffu, i0, o);
            float ov1 = __shfl_xor_sync(0xffffffffu, v1, o);
            int   oi1 = __shfl_xor_sync(0xffffffffu, i1, o);
            ins2(v0, i0, v1, i1, ov0, oi0);
            ins2(v0, i0, v1, i1, ov1, oi1);
        }
        if (tig == 0) {
            int row = mw + (i >> 1) * 16 + gq + (i & 1) * 8;
            int half = (w & 1) * 256;
            sB0v[half + row] = v0; sB0i[half + row] = i0;
            sB1v[half + row] = v1; sB1i[half + row] = i1;
        }
    }
    __syncthreads();
    {
        float v0 = sB0v[tid], v1 = sB1v[tid];
        int i0 = sB0i[tid], i1 = sB1i[tid];
        ins2(v0, i0, v1, i1, sB0v[256 + tid], sB0i[256 + tid]);
        ins2(v0, i0, v1, i1, sB1v[256 + tid], sB1i[256 + tid]);
        int n = cid * 256 + tid;
        g_idx[n] = i0;
        out[OFF_IDX + n] = (float)i0;
        if (__fadd_rn(v1, -v0) < EPS_GAP) {
            g_idx2[n] = i1;
            int pos = atomicAdd(&g_fixn, 1);
            g_fixlist[pos] = n;
        }
    }
}

// ---------------- near-tie rescue: exact fp32 recompute of the 2 contenders ----------------
__global__ __launch_bounds__(256) void k_fix(const float* __restrict__ z,
                                             const float* __restrict__ E,
                                             float* __restrict__ out) {
    int wid = (blockIdx.x * 256 + threadIdx.x) >> 5;
    int lane = threadIdx.x & 31;
    int cnt = g_fixn;
    for (int e = wid; e < cnt; e += (gridDim.x * 256) >> 5) {
        int n = g_fixlist[e];
        int ia = g_idx[n], ib = g_idx2[n];
        int b = n >> 10, hw = n & 1023;
        const float* zp = z + (size_t)b * DIM * HW + hw;
        const float* ea = E + (size_t)ia * DIM;
        const float* eb = E + (size_t)ib * DIM;
        float da = 0.f, db = 0.f;
#pragma unroll
        for (int j = 0; j < 8; j++) {
            int d = lane + j * 32;
            float zv = zp[(size_t)d * HW];
            da = fmaf(zv, ea[d], da);
            db = fmaf(zv, eb[d], db);
        }
#pragma unroll
        for (int o = 16; o; o >>= 1) {
            da += __shfl_xor_sync(0xffffffffu, da, o);
            db += __shfl_xor_sync(0xffffffffu, db, o);
        }
        if (!lane) {
            float zz = g_zz[n];
            float distA = __fadd_rn(__fadd_rn(zz, -__fmul_rn(2.0f, da)), g_ee[ia]);
            float distB = __fadd_rn(__fadd_rn(zz, -__fmul_rn(2.0f, db)), g_ee[ib]);
            int wnr = (distB < distA || (distB == distA && ib < ia)) ? ib : ia;
            g_idx[n] = wnr;
            out[OFF_IDX + n] = (float)wnr;
        }
    }
}

// ---------------- fused epilogue: gather z_q, loss, counts, embed_sum ----------------
__global__ __launch_bounds__(256)
void k_epi(const float* __restrict__ z, const float* __restrict__ E,
           float* __restrict__ out) {
    __shared__ float tile[64 * 129];
    __shared__ float lred[8];
    const int tid = threadIdx.x;
    const int n0 = blockIdx.x * 128;
    const int b = n0 >> 10, hw0 = n0 & 1023;
    const float* zb = z + (size_t)b * DIM * HW + hw0;
    float* ob = out + OFF_ZQ + (size_t)b * DIM * HW + hw0;
    const int w = tid >> 5, lane = tid & 31;
    float lacc = 0.f;

    for (int c = 0; c < 4; c++) {
#pragma unroll
        for (int r = 0; r < 32; r++) {
            int idx = tid + r * 256;
            int dd = idx >> 7, pt = idx & 127;
            tile[dd * 129 + pt] = zb[(size_t)(c * 64 + dd) * HW + pt];
        }
        __syncthreads();
        for (int q = 0; q < 16; q++) {
            int pt = w * 16 + q;
            int code = g_idx[n0 + pt];
            int d = c * 64 + lane * 2;
            float2 ev = *reinterpret_cast<const float2*>(&E[(size_t)code * DIM + d]);
            float z0 = tile[(lane * 2) * 129 + pt];
            float z1 = tile[(lane * 2 + 1) * 129 + pt];
            float d0 = __fadd_rn(z0, -ev.x);
            float d1 = __fadd_rn(z1, -ev.y);
            lacc = fmaf(d0, d0, lacc);
            lacc = fmaf(d1, d1, lacc);
            float o0 = __fadd_rn(z0, __fadd_rn(ev.x, -z0));
            float o1 = __fadd_rn(z1, __fadd_rn(ev.y, -z1));
            tile[(lane * 2) * 129 + pt] = o0;
            tile[(lane * 2 + 1) * 129 + pt] = o1;
            atomicAdd(reinterpret_cast<float2*>(&g_es[(size_t)code * DIM + d]),
                      make_float2(z0, z1));
        }
        __syncthreads();
#pragma unroll
        for (int r = 0; r < 32; r++) {
            int idx = tid + r * 256;
            int dd = idx >> 7, pt = idx & 127;
            ob[(size_t)(c * 64 + dd) * HW + pt] = tile[dd * 129 + pt];
        }
        __syncthreads();
    }
    if (tid < 128) atomicAdd(&g_counts[g_idx[n0 + tid]], 1.0f);
#pragma unroll
    for (int o = 16; o; o >>= 1) lacc += __shfl_xor_sync(0xffffffffu, lacc, o);
    if (!lane) lred[w] = lacc;
    __syncthreads();
    if (tid == 0) {
        float s = 0.f;
#pragma unroll
        for (int i = 0; i < 8; i++) s += lred[i];
        atomicAdd(&g_loss, s);
    }
}

// ---------------- new_cs + n + loss scalar ----------------
__global__ void k4a(const float* __restrict__ ema_cs, float* __restrict__ out) {
    __shared__ float red[32];
    int k = threadIdx.x;
    float ncs = __fadd_rn(__fmul_rn(0.99f, ema_cs[k]), __fmul_rn(0.01f, g_counts[k]));
    g_newcs[k] = ncs;
    out[OFF_CS + k] = ncs;
    float s = ncs;
#pragma unroll
    for (int o = 16; o; o >>= 1) s += __shfl_xor_sync(0xffffffffu, s, o);
    if ((k & 31) == 0) red[k >> 5] = s;
    __syncthreads();
    if (k < 32) {
        float v = red[k];
#pragma unroll
        for (int o = 16; o; o >>= 1) v += __shfl_xor_sync(0xffffffffu, v, o);
        if (!k) {
            g_nsum = v;
            out[OFF_LOSS] = g_loss * (1.0f / 8388608.0f);
        }
    }
}

// ---------------- new_es + new_embedding ----------------
__global__ void k4b(const float* __restrict__ ema_es, float* __restrict__ out) {
    int k = blockIdx.x, d = threadIdx.x;
    size_t i = (size_t)k * DIM + d;
    float es = __fadd_rn(__fmul_rn(0.99f, ema_es[i]), __fmul_rn(0.01f, g_es[i]));
    out[OFF_ES + i] = es;
    float n = g_nsum;
    float cs = __fmul_rn(__fdiv_rn(__fadd_rn(g_newcs[k], 1e-5f),
                                   __fadd_rn(n, 0.01024f)), n);
    out[OFF_EMB + i] = __fdiv_rn(es, cs);
}

extern "C" void kernel_launch(void* const* d_in, const int* in_sizes, int n_in,
                              void* d_out, int out_size) {
    const float* z      = (const float*)d_in[0];
    const float* E      = (const float*)d_in[1];
    const float* ema_cs = (const float*)d_in[2];
    const float* ema_es = (const float*)d_in[3];
    float* out = (float*)d_out;

    cudaFuncSetAttribute(k_gemm, cudaFuncAttributeMaxDynamicSharedMemorySize, SMEM_GEMM);

    k_zero<<<(KCODES * DIM + KCODES + 3 + 255) / 256, 256>>>();
    k_ee<<<128, 256>>>(E);
    k_zz<<<128, 256>>>(z);
    k_split_z<<<8192, 256>>>((const float4*)z);
    k_split_eT<<<1024, 256>>>(E);
    k_gemm<<<128, 256, SMEM_GEMM>>>(out);
    k_fix<<<64, 256>>>(z, E, out);
    k_epi<<<NPTS / 128, 256>>>(z, E, out);
    k4a<<<1, 1024>>>(ema_cs, out);
    k4b<<<KCODES, DIM>>>(ema_es, out);
}